// round 2
// baseline (speedup 1.0000x reference)
#include <cuda_runtime.h>
#include <math.h>

#define T_SEQ 2048
#define DM    4096
#define NH    32
#define NKV   8
#define DH    128
#define DKV   1024   // NKV * DH

// ---------------- scratch (static device globals; no allocation) -------------
__device__ float  g_Q[T_SEQ * DM];     // 32 MB  [t, h*128+d]
__device__ float  g_K[T_SEQ * DKV];    //  8 MB  [t, kvh*128+d]
__device__ float  g_V[T_SEQ * DKV];    //  8 MB
__device__ float  g_ctx[T_SEQ * DM];   // 32 MB
__device__ double g_freq[64];

// ---------------- RoPE frequency table (Llama3 scaling), fp64 ---------------
__global__ void init_freq_kernel() {
    int i = threadIdx.x;
    if (i >= 64) return;
    const double PI = 3.14159265358979323846;
    double idx  = (double)i / 64.0;                       // (2i)/128
    double freq = (1.0 / (2.0 * PI)) * exp(-idx * log(500000.0));
    double flow  = 1.0 / 8192.0;
    double fhigh = 4.0 / 8192.0;
    double scaled = (freq < flow) ? freq / 32.0 : freq;
    double smooth = (8192.0 * freq - 1.0) / 3.0;
    smooth = fmin(fmax(smooth, 0.0), 1.0);
    double fsm = (1.0 - smooth) * (freq / 32.0) + smooth * freq;
    g_freq[i] = (freq >= flow && freq <= fhigh) ? fsm : scaled;
}

// ---------------- RoPE application (in place) --------------------------------
__global__ void rope_kernel(float* __restrict__ X, int nheads, int total) {
    int idx = blockIdx.x * blockDim.x + threadIdx.x;
    if (idx >= total) return;
    int i = idx & 63;
    int h = (idx >> 6) % nheads;
    int t = idx / (64 * nheads);

    const double TWO_PI = 6.28318530717958647692;
    double phase = TWO_PI * (double)t * g_freq[i];
    double sd, cd;
    sincos(phase, &sd, &cd);
    float c = (float)cd, s = (float)sd;

    int base = t * (nheads * DH) + h * DH;
    float x1 = X[base + i];
    float x2 = X[base + i + 64];
    X[base + i]      = x1 * c - x2 * s;   // x*cos + rotate_half(x)*sin, first half
    X[base + i + 64] = x2 * c + x1 * s;   // second half
}

// ---------------- tiled fp32 GEMM: C[M,N] = A[M,K] @ B[K,N] ------------------
#define BM 128
#define BN 128
#define BK 16

__global__ __launch_bounds__(256)
void sgemm_kernel(const float* __restrict__ A, const float* __restrict__ B,
                  float* __restrict__ C, int M, int N, int K) {
    __shared__ float As[BK][BM];   // transposed A tile
    __shared__ float Bs[BK][BN];

    int tid = threadIdx.x;
    int tm = (tid >> 4) << 3;      // 0..120, microtile row base
    int tn = (tid & 15) << 3;      // 0..120, microtile col base

    const float* Ap = A + blockIdx.y * BM * K;
    const float* Bp = B + blockIdx.x * BN;

    int aRow = tid >> 2;           // 0..63
    int aCol = (tid & 3) << 2;     // 0,4,8,12
    int bRow = tid >> 5;           // 0..7
    int bCol = (tid & 31) << 2;    // 0..124

    float acc[8][8];
#pragma unroll
    for (int i = 0; i < 8; i++)
#pragma unroll
        for (int j = 0; j < 8; j++) acc[i][j] = 0.f;

    for (int k0 = 0; k0 < K; k0 += BK) {
        float4 a0 = *(const float4*)(Ap + aRow * K + k0 + aCol);
        float4 a1 = *(const float4*)(Ap + (aRow + 64) * K + k0 + aCol);
        float4 b0 = *(const float4*)(Bp + (k0 + bRow) * N + bCol);
        float4 b1 = *(const float4*)(Bp + (k0 + bRow + 8) * N + bCol);

        As[aCol + 0][aRow] = a0.x; As[aCol + 1][aRow] = a0.y;
        As[aCol + 2][aRow] = a0.z; As[aCol + 3][aRow] = a0.w;
        As[aCol + 0][aRow + 64] = a1.x; As[aCol + 1][aRow + 64] = a1.y;
        As[aCol + 2][aRow + 64] = a1.z; As[aCol + 3][aRow + 64] = a1.w;
        *(float4*)&Bs[bRow][bCol]     = b0;
        *(float4*)&Bs[bRow + 8][bCol] = b1;
        __syncthreads();

#pragma unroll
        for (int kk = 0; kk < BK; kk++) {
            float ar[8], br[8];
            *(float4*)&ar[0] = *(float4*)&As[kk][tm];
            *(float4*)&ar[4] = *(float4*)&As[kk][tm + 4];
            *(float4*)&br[0] = *(float4*)&Bs[kk][tn];
            *(float4*)&br[4] = *(float4*)&Bs[kk][tn + 4];
#pragma unroll
            for (int i = 0; i < 8; i++)
#pragma unroll
                for (int j = 0; j < 8; j++)
                    acc[i][j] = fmaf(ar[i], br[j], acc[i][j]);
        }
        __syncthreads();
    }

    float* Cp = C + (blockIdx.y * BM + tm) * N + blockIdx.x * BN + tn;
#pragma unroll
    for (int i = 0; i < 8; i++) {
        *(float4*)(Cp + i * N)     = make_float4(acc[i][0], acc[i][1], acc[i][2], acc[i][3]);
        *(float4*)(Cp + i * N + 4) = make_float4(acc[i][4], acc[i][5], acc[i][6], acc[i][7]);
    }
}

// ---------------- flash attention, fp32, causal, GQA -------------------------
// Block: 64 q-rows of one head.  Tiles of 64 kv rows.  256 threads as 16x16.
// Thread (ty,tx) owns S rows {ty+16i} x cols {tx+16j}, and O rows {ty+16i} x
// d-cols [tx*8, tx*8+8).  Strided row mapping makes the K-tile float4 LDS
// conflict-free (row stride 132 -> start-bank step 4 across tx).
#define AD 132                      // padded row stride for Q/K/V tiles
#define SD 65                       // padded row stride for S tile
#define FLASH_SMEM ((3 * 64 * AD + 64 * SD) * 4)

__global__ __launch_bounds__(256)
void flash_kernel(const float* __restrict__ Q, const float* __restrict__ K,
                  const float* __restrict__ V, float* __restrict__ ctx) {
    extern __shared__ float sm[];
    float* Qs = sm;
    float* Ks = sm + 64 * AD;
    float* Vs = sm + 2 * 64 * AD;
    float* Ss = sm + 3 * 64 * AD;
    __shared__ float m_s[64], l_s[64], corr_s[64];

    const int qt  = blockIdx.x;      // q tile 0..31
    const int h   = blockIdx.y;      // head 0..31
    const int kvh = h >> 2;
    const int tid = threadIdx.x;
    const int ty  = tid >> 4;        // 0..15
    const int tx  = tid & 15;        // 0..15
    const float scale = 0.08838834764831845f;   // 1/sqrt(128)

    // load Q tile (scaled)
#pragma unroll
    for (int it = 0; it < 8; it++) {
        int idx = tid + it * 256;            // 0..2047 float4s
        int row = idx >> 5, c4 = (idx & 31) << 2;
        float4 v = *(const float4*)(Q + (qt * 64 + row) * DM + h * DH + c4);
        v.x *= scale; v.y *= scale; v.z *= scale; v.w *= scale;
        *(float4*)&Qs[row * AD + c4] = v;
    }
    if (tid < 64) { m_s[tid] = -1e30f; l_s[tid] = 0.f; }

    float acc[4][8];
#pragma unroll
    for (int i = 0; i < 4; i++)
#pragma unroll
        for (int j = 0; j < 8; j++) acc[i][j] = 0.f;
    __syncthreads();

    for (int kt = 0; kt <= qt; kt++) {
        // load K,V tiles
#pragma unroll
        for (int it = 0; it < 8; it++) {
            int idx = tid + it * 256;
            int row = idx >> 5, c4 = (idx & 31) << 2;
            int g = (kt * 64 + row) * DKV + kvh * DH + c4;
            *(float4*)&Ks[row * AD + c4] = *(const float4*)(K + g);
            *(float4*)&Vs[row * AD + c4] = *(const float4*)(V + g);
        }
        __syncthreads();

        // S = (Q*scale) @ K^T   (4x4 per thread over d=128)
        float s[4][4];
#pragma unroll
        for (int i = 0; i < 4; i++)
#pragma unroll
            for (int j = 0; j < 4; j++) s[i][j] = 0.f;

#pragma unroll 8
        for (int d = 0; d < DH; d += 4) {
            float4 q4[4], k4[4];
#pragma unroll
            for (int i = 0; i < 4; i++) q4[i] = *(float4*)&Qs[(ty + 16 * i) * AD + d];
#pragma unroll
            for (int j = 0; j < 4; j++) k4[j] = *(float4*)&Ks[(tx + 16 * j) * AD + d];
#pragma unroll
            for (int i = 0; i < 4; i++)
#pragma unroll
                for (int j = 0; j < 4; j++) {
                    s[i][j] = fmaf(q4[i].x, k4[j].x, s[i][j]);
                    s[i][j] = fmaf(q4[i].y, k4[j].y, s[i][j]);
                    s[i][j] = fmaf(q4[i].z, k4[j].z, s[i][j]);
                    s[i][j] = fmaf(q4[i].w, k4[j].w, s[i][j]);
                }
        }

        // store S (mask only on diagonal tile)
        if (kt == qt) {
#pragma unroll
            for (int i = 0; i < 4; i++)
#pragma unroll
                for (int j = 0; j < 4; j++) {
                    int rq = (ty + 16 * i);
                    int rk = (tx + 16 * j);
                    Ss[rq * SD + rk] = (rk <= rq) ? s[i][j] : -1e30f;
                }
        } else {
#pragma unroll
            for (int i = 0; i < 4; i++)
#pragma unroll
                for (int j = 0; j < 4; j++)
                    Ss[(ty + 16 * i) * SD + (tx + 16 * j)] = s[i][j];
        }
        __syncthreads();

        // online softmax row update (one thread per row)
        if (tid < 64) {
            int r = tid;
            float m_old = m_s[r];
            float mx = m_old;
#pragma unroll 8
            for (int c = 0; c < 64; c++) mx = fmaxf(mx, Ss[r * SD + c]);
            float corr = __expf(m_old - mx);
            float sum = 0.f;
#pragma unroll 8
            for (int c = 0; c < 64; c++) {
                float p = __expf(Ss[r * SD + c] - mx);
                Ss[r * SD + c] = p;
                sum += p;
            }
            m_s[r] = mx;
            l_s[r] = l_s[r] * corr + sum;
            corr_s[r] = corr;
        }
        __syncthreads();

        // rescale accumulators, then acc += P @ V
#pragma unroll
        for (int i = 0; i < 4; i++) {
            float cr = corr_s[ty + 16 * i];
#pragma unroll
            for (int j = 0; j < 8; j++) acc[i][j] *= cr;
        }

#pragma unroll 4
        for (int c = 0; c < 64; c++) {
            float4 v0 = *(float4*)&Vs[c * AD + tx * 8];
            float4 v1 = *(float4*)&Vs[c * AD + tx * 8 + 4];
#pragma unroll
            for (int i = 0; i < 4; i++) {
                float p = Ss[(ty + 16 * i) * SD + c];
                acc[i][0] = fmaf(p, v0.x, acc[i][0]);
                acc[i][1] = fmaf(p, v0.y, acc[i][1]);
                acc[i][2] = fmaf(p, v0.z, acc[i][2]);
                acc[i][3] = fmaf(p, v0.w, acc[i][3]);
                acc[i][4] = fmaf(p, v1.x, acc[i][4]);
                acc[i][5] = fmaf(p, v1.y, acc[i][5]);
                acc[i][6] = fmaf(p, v1.z, acc[i][6]);
                acc[i][7] = fmaf(p, v1.w, acc[i][7]);
            }
        }
        __syncthreads();
    }

    // normalize and write ctx[t, h*128+d]
#pragma unroll
    for (int i = 0; i < 4; i++) {
        int r = ty + 16 * i;
        float inv = 1.0f / l_s[r];
        float* cp = ctx + (qt * 64 + r) * DM + h * DH + tx * 8;
        *(float4*)cp       = make_float4(acc[i][0] * inv, acc[i][1] * inv,
                                         acc[i][2] * inv, acc[i][3] * inv);
        *(float4*)(cp + 4) = make_float4(acc[i][4] * inv, acc[i][5] * inv,
                                         acc[i][6] * inv, acc[i][7] * inv);
    }
}

// ---------------- launch ------------------------------------------------------
extern "C" void kernel_launch(void* const* d_in, const int* in_sizes, int n_in,
                              void* d_out, int out_size) {
    const float* resid = (const float*)d_in[0];
    const float* Wq    = (const float*)d_in[1];
    const float* Wk    = (const float*)d_in[2];
    const float* Wv    = (const float*)d_in[3];
    const float* Wo    = (const float*)d_in[4];
    float* out = (float*)d_out;

    float *gQ, *gK, *gV, *gC;
    cudaGetSymbolAddress((void**)&gQ, g_Q);
    cudaGetSymbolAddress((void**)&gK, g_K);
    cudaGetSymbolAddress((void**)&gV, g_V);
    cudaGetSymbolAddress((void**)&gC, g_ctx);

    cudaFuncSetAttribute(flash_kernel,
                         cudaFuncAttributeMaxDynamicSharedMemorySize, FLASH_SMEM);

    init_freq_kernel<<<1, 64>>>();

    dim3 blk(256);
    // Q = resid @ Wq
    sgemm_kernel<<<dim3(DM / BN, T_SEQ / BM), blk>>>(resid, Wq, gQ, T_SEQ, DM, DM);
    // K = resid @ Wk
    sgemm_kernel<<<dim3(DKV / BN, T_SEQ / BM), blk>>>(resid, Wk, gK, T_SEQ, DKV, DM);
    // V = resid @ Wv
    sgemm_kernel<<<dim3(DKV / BN, T_SEQ / BM), blk>>>(resid, Wv, gV, T_SEQ, DKV, DM);

    int totQ = T_SEQ * NH * 64;
    rope_kernel<<<(totQ + 255) / 256, 256>>>(gQ, NH, totQ);
    int totK = T_SEQ * NKV * 64;
    rope_kernel<<<(totK + 255) / 256, 256>>>(gK, NKV, totK);

    flash_kernel<<<dim3(T_SEQ / 64, NH), blk, FLASH_SMEM>>>(gQ, gK, gV, gC);

    // out = ctx @ Wo
    sgemm_kernel<<<dim3(DM / BN, T_SEQ / BM), blk>>>(gC, Wo, out, T_SEQ, DM, DM);
}

// round 6
// speedup vs baseline: 1.8583x; 1.8583x over previous
#include <cuda_runtime.h>
#include <cuda_bf16.h>
#include <math.h>
#include <cstdint>

#define T_SEQ 2048
#define DM    4096
#define NH    32
#define NKV   8
#define DH    128
#define DKV   1024   // NKV * DH

// ---------------- scratch (static device globals; no allocation) -------------
__device__ float  g_Q[T_SEQ * DM];     // [t, h*128+d]
__device__ float  g_K[T_SEQ * DKV];
__device__ float  g_V[T_SEQ * DKV];
__device__ float  g_ctx[T_SEQ * DM];
__device__ double g_freq[64];

// bf16 hi/lo splits of activations (K-major [M,K])
__device__ __nv_bfloat16 g_r_hi[T_SEQ * DM];
__device__ __nv_bfloat16 g_r_lo[T_SEQ * DM];
__device__ __nv_bfloat16 g_c_hi[T_SEQ * DM];
__device__ __nv_bfloat16 g_c_lo[T_SEQ * DM];
// transposed + split weights [N,K]
__device__ __nv_bfloat16 g_Wq_hi[DM * DM];
__device__ __nv_bfloat16 g_Wq_lo[DM * DM];
__device__ __nv_bfloat16 g_Wk_hi[DKV * DM];
__device__ __nv_bfloat16 g_Wk_lo[DKV * DM];
__device__ __nv_bfloat16 g_Wv_hi[DKV * DM];
__device__ __nv_bfloat16 g_Wv_lo[DKV * DM];
__device__ __nv_bfloat16 g_Wo_hi[DM * DM];
__device__ __nv_bfloat16 g_Wo_lo[DM * DM];

// ---------------- small PTX helpers (all valid on plain sm_100) --------------
__device__ __forceinline__ uint32_t smem_to_u32(const void* p) {
    uint32_t a;
    asm("{ .reg .u64 t; cvta.to.shared.u64 t, %1; cvt.u32.u64 %0, t; }" : "=r"(a) : "l"(p));
    return a;
}
__device__ __forceinline__ void cp_async16(uint32_t d, const void* g) {
    asm volatile("cp.async.cg.shared.global [%0], [%1], 16;" :: "r"(d), "l"(g));
}
#define CP_COMMIT() asm volatile("cp.async.commit_group;" ::: "memory")
#define CP_WAIT(n)  asm volatile("cp.async.wait_group %0;" :: "n"(n) : "memory")

__device__ __forceinline__ void ldmatrix_x4(uint32_t* r, uint32_t addr) {
    asm volatile("ldmatrix.sync.aligned.m8n8.x4.shared.b16 {%0,%1,%2,%3}, [%4];"
                 : "=r"(r[0]), "=r"(r[1]), "=r"(r[2]), "=r"(r[3]) : "r"(addr));
}
__device__ __forceinline__ void ldmatrix_x2(uint32_t* r, uint32_t addr) {
    asm volatile("ldmatrix.sync.aligned.m8n8.x2.shared.b16 {%0,%1}, [%2];"
                 : "=r"(r[0]), "=r"(r[1]) : "r"(addr));
}
__device__ __forceinline__ void mma_bf16(float* d, const uint32_t* a, const uint32_t* b) {
    asm volatile("mma.sync.aligned.m16n8k16.row.col.f32.bf16.bf16.f32 "
                 "{%0,%1,%2,%3}, {%4,%5,%6,%7}, {%8,%9}, {%0,%1,%2,%3};"
                 : "+f"(d[0]), "+f"(d[1]), "+f"(d[2]), "+f"(d[3])
                 : "r"(a[0]), "r"(a[1]), "r"(a[2]), "r"(a[3]), "r"(b[0]), "r"(b[1]));
}

// ---------------- RoPE frequency table (Llama3 scaling), fp64 ---------------
__global__ void init_freq_kernel() {
    int i = threadIdx.x;
    if (i >= 64) return;
    const double PI = 3.14159265358979323846;
    double idx  = (double)i / 64.0;
    double freq = (1.0 / (2.0 * PI)) * exp(-idx * log(500000.0));
    double flow  = 1.0 / 8192.0;
    double fhigh = 4.0 / 8192.0;
    double scaled = (freq < flow) ? freq / 32.0 : freq;
    double smooth = (8192.0 * freq - 1.0) / 3.0;
    smooth = fmin(fmax(smooth, 0.0), 1.0);
    double fsm = (1.0 - smooth) * (freq / 32.0) + smooth * freq;
    g_freq[i] = (freq >= flow && freq <= fhigh) ? fsm : scaled;
}

// ---------------- RoPE application (in place) --------------------------------
__global__ void rope_kernel(float* __restrict__ X, int nheads, int total) {
    int idx = blockIdx.x * blockDim.x + threadIdx.x;
    if (idx >= total) return;
    int i = idx & 63;
    int h = (idx >> 6) % nheads;
    int t = idx / (64 * nheads);
    const double TWO_PI = 6.28318530717958647692;
    double phase = TWO_PI * (double)t * g_freq[i];
    double sd, cd;
    sincos(phase, &sd, &cd);
    float c = (float)cd, s = (float)sd;
    int base = t * (nheads * DH) + h * DH;
    float x1 = X[base + i];
    float x2 = X[base + i + 64];
    X[base + i]      = x1 * c - x2 * s;
    X[base + i + 64] = x2 * c + x1 * s;
}

// ---------------- split fp32 -> bf16 hi + lo ---------------------------------
__global__ void split_kernel(const float* __restrict__ X,
                             __nv_bfloat16* __restrict__ hi,
                             __nv_bfloat16* __restrict__ lo, int n) {
    int i = blockIdx.x * blockDim.x + threadIdx.x;
    if (i >= n) return;
    float x = X[i];
    __nv_bfloat16 h = __float2bfloat16(x);
    hi[i] = h;
    lo[i] = __float2bfloat16(x - __bfloat162float(h));
}

// ---------------- transpose + split: W[K,N] -> hiT/loT[N,K] ------------------
__global__ void transpose_split_kernel(const float* __restrict__ W,
                                       __nv_bfloat16* __restrict__ hiT,
                                       __nv_bfloat16* __restrict__ loT,
                                       int K, int N) {
    __shared__ float t[32][33];
    int tx = threadIdx.x, ty = threadIdx.y;       // (32, 8)
    int n0 = blockIdx.x * 32, k0 = blockIdx.y * 32;
#pragma unroll
    for (int j = 0; j < 4; j++) {
        int k = k0 + ty + j * 8;
        t[ty + j * 8][tx] = W[(size_t)k * N + n0 + tx];
    }
    __syncthreads();
#pragma unroll
    for (int j = 0; j < 4; j++) {
        int n = n0 + ty + j * 8;
        float x = t[tx][ty + j * 8];
        __nv_bfloat16 h = __float2bfloat16(x);
        size_t o = (size_t)n * K + k0 + tx;
        hiT[o] = h;
        loT[o] = __float2bfloat16(x - __bfloat162float(h));
    }
}

// ---------------- bf16 3-split GEMM on mma.sync (HMMA) -----------------------
// C[M,N] = A[M,K] @ W[K,N]; A as (Ahi+Alo)[M,K], W as transposed (Bhi+Blo)[N,K].
// Block tile 128x128, BK=32, 8 warps (warp tile 64x32), cp.async double buffer.
#define GKC    32
#define ROWB   80                 // 64B data + 16B pad: conflict-free ldmatrix
#define TILEB  (128 * ROWB)       // 10240 B
#define STAGEB (4 * TILEB)        // Ahi, Alo, Bhi, Blo
#define GEMM_SMEM (2 * STAGEB)    // 81920 B

__global__ __launch_bounds__(256)
void gemm_mma_kernel(const __nv_bfloat16* __restrict__ Ahi,
                     const __nv_bfloat16* __restrict__ Alo,
                     const __nv_bfloat16* __restrict__ Bhi,
                     const __nv_bfloat16* __restrict__ Blo,
                     float* __restrict__ C, int M, int N, int K) {
    extern __shared__ char smem[];
    const uint32_t sbase = smem_to_u32(smem);
    const int tid = threadIdx.x;
    const int wid = tid >> 5, lane = tid & 31;
    const int bm = blockIdx.y, bn = blockIdx.x;
    const int wm = wid & 1, wn = wid >> 1;       // warp grid 2(M) x 4(N)
    const int nch = K / GKC;

    const __nv_bfloat16* srcs[4] = {
        Ahi + (size_t)bm * 128 * K, Alo + (size_t)bm * 128 * K,
        Bhi + (size_t)bn * 128 * K, Blo + (size_t)bn * 128 * K };

    // async-load one K-chunk into stage s
    auto load_stage = [&](int ic, int s) {
        const int k0 = ic * GKC;
#pragma unroll
        for (int t4 = 0; t4 < 4; t4++) {
            const __nv_bfloat16* src = srcs[t4] + k0;
            uint32_t dstb = sbase + s * STAGEB + t4 * TILEB;
#pragma unroll
            for (int it = 0; it < 2; it++) {
                int idx = tid + it * 256;            // 0..511
                int row = idx >> 2, c = idx & 3;     // 4 x 16B per 64B row
                cp_async16(dstb + row * ROWB + c * 16,
                           src + (size_t)row * K + c * 8);
            }
        }
    };

    float acc[16][4];
#pragma unroll
    for (int i = 0; i < 16; i++)
#pragma unroll
        for (int j = 0; j < 4; j++) acc[i][j] = 0.f;

    load_stage(0, 0);
    CP_COMMIT();

    for (int ic = 0; ic < nch; ic++) {
        const int s = ic & 1;
        if (ic + 1 < nch) { load_stage(ic + 1, s ^ 1); CP_COMMIT(); CP_WAIT(1); }
        else              { CP_WAIT(0); }
        __syncthreads();

        const uint32_t abase = sbase + s * STAGEB;           // Ahi tile
        const uint32_t bbase = abase + 2 * TILEB;            // Bhi tile
#pragma unroll
        for (int ks = 0; ks < 2; ks++) {
            uint32_t ah[4][4], al[4][4];
#pragma unroll
            for (int mt = 0; mt < 4; mt++) {
                int row = wm * 64 + mt * 16 + (lane & 15);
                uint32_t off = row * ROWB + ks * 32 + ((lane >> 4) << 4);
                ldmatrix_x4(ah[mt], abase + off);
                ldmatrix_x4(al[mt], abase + TILEB + off);
            }
            uint32_t bh[4][2], bl[4][2];
#pragma unroll
            for (int nt = 0; nt < 4; nt++) {
                int row = wn * 32 + nt * 8 + (lane & 7);
                uint32_t off = row * ROWB + ks * 32 + (((lane >> 3) & 1) << 4);
                ldmatrix_x2(bh[nt], bbase + off);
                ldmatrix_x2(bl[nt], bbase + TILEB + off);
            }
#pragma unroll
            for (int mt = 0; mt < 4; mt++)
#pragma unroll
                for (int nt = 0; nt < 4; nt++) {
                    mma_bf16(acc[mt * 4 + nt], ah[mt], bh[nt]);   // hi*hi
                    mma_bf16(acc[mt * 4 + nt], ah[mt], bl[nt]);   // hi*lo
                    mma_bf16(acc[mt * 4 + nt], al[mt], bh[nt]);   // lo*hi
                }
        }
        __syncthreads();
    }

    // epilogue: fragment layout -> C
    const int g = lane >> 2, t2 = (lane & 3) * 2;
#pragma unroll
    for (int mt = 0; mt < 4; mt++) {
        int r0 = bm * 128 + wm * 64 + mt * 16 + g;
#pragma unroll
        for (int nt = 0; nt < 4; nt++) {
            int c0 = bn * 128 + wn * 32 + nt * 8 + t2;
            float* p = C + (size_t)r0 * N + c0;
            *(float2*)p           = make_float2(acc[mt * 4 + nt][0], acc[mt * 4 + nt][1]);
            *(float2*)(p + 8 * N) = make_float2(acc[mt * 4 + nt][2], acc[mt * 4 + nt][3]);
        }
    }
}

// ---------------- flash attention, fp32, causal, GQA (unchanged) -------------
#define AD 132
#define SD 65
#define FLASH_SMEM ((3 * 64 * AD + 64 * SD) * 4)

__global__ __launch_bounds__(256)
void flash_kernel(const float* __restrict__ Q, const float* __restrict__ K,
                  const float* __restrict__ V, float* __restrict__ ctx) {
    extern __shared__ float sm[];
    float* Qs = sm;
    float* Ks = sm + 64 * AD;
    float* Vs = sm + 2 * 64 * AD;
    float* Ss = sm + 3 * 64 * AD;
    __shared__ float m_s[64], l_s[64], corr_s[64];

    const int qt  = blockIdx.x;
    const int h   = blockIdx.y;
    const int kvh = h >> 2;
    const int tid = threadIdx.x;
    const int ty  = tid >> 4;
    const int tx  = tid & 15;
    const float scale = 0.08838834764831845f;

#pragma unroll
    for (int it = 0; it < 8; it++) {
        int idx = tid + it * 256;
        int row = idx >> 5, c4 = (idx & 31) << 2;
        float4 v = *(const float4*)(Q + (qt * 64 + row) * DM + h * DH + c4);
        v.x *= scale; v.y *= scale; v.z *= scale; v.w *= scale;
        *(float4*)&Qs[row * AD + c4] = v;
    }
    if (tid < 64) { m_s[tid] = -1e30f; l_s[tid] = 0.f; }

    float acc[4][8];
#pragma unroll
    for (int i = 0; i < 4; i++)
#pragma unroll
        for (int j = 0; j < 8; j++) acc[i][j] = 0.f;
    __syncthreads();

    for (int kt = 0; kt <= qt; kt++) {
#pragma unroll
        for (int it = 0; it < 8; it++) {
            int idx = tid + it * 256;
            int row = idx >> 5, c4 = (idx & 31) << 2;
            int g = (kt * 64 + row) * DKV + kvh * DH + c4;
            *(float4*)&Ks[row * AD + c4] = *(const float4*)(K + g);
            *(float4*)&Vs[row * AD + c4] = *(const float4*)(V + g);
        }
        __syncthreads();

        float s[4][4];
#pragma unroll
        for (int i = 0; i < 4; i++)
#pragma unroll
            for (int j = 0; j < 4; j++) s[i][j] = 0.f;

#pragma unroll 8
        for (int d = 0; d < DH; d += 4) {
            float4 q4[4], k4[4];
#pragma unroll
            for (int i = 0; i < 4; i++) q4[i] = *(float4*)&Qs[(ty + 16 * i) * AD + d];
#pragma unroll
            for (int j = 0; j < 4; j++) k4[j] = *(float4*)&Ks[(tx + 16 * j) * AD + d];
#pragma unroll
            for (int i = 0; i < 4; i++)
#pragma unroll
                for (int j = 0; j < 4; j++) {
                    s[i][j] = fmaf(q4[i].x, k4[j].x, s[i][j]);
                    s[i][j] = fmaf(q4[i].y, k4[j].y, s[i][j]);
                    s[i][j] = fmaf(q4[i].z, k4[j].z, s[i][j]);
                    s[i][j] = fmaf(q4[i].w, k4[j].w, s[i][j]);
                }
        }

        if (kt == qt) {
#pragma unroll
            for (int i = 0; i < 4; i++)
#pragma unroll
                for (int j = 0; j < 4; j++) {
                    int rq = (ty + 16 * i);
                    int rk = (tx + 16 * j);
                    Ss[rq * SD + rk] = (rk <= rq) ? s[i][j] : -1e30f;
                }
        } else {
#pragma unroll
            for (int i = 0; i < 4; i++)
#pragma unroll
                for (int j = 0; j < 4; j++)
                    Ss[(ty + 16 * i) * SD + (tx + 16 * j)] = s[i][j];
        }
        __syncthreads();

        if (tid < 64) {
            int r = tid;
            float m_old = m_s[r];
            float mx = m_old;
#pragma unroll 8
            for (int c = 0; c < 64; c++) mx = fmaxf(mx, Ss[r * SD + c]);
            float corr = __expf(m_old - mx);
            float sum = 0.f;
#pragma unroll 8
            for (int c = 0; c < 64; c++) {
                float p = __expf(Ss[r * SD + c] - mx);
                Ss[r * SD + c] = p;
                sum += p;
            }
            m_s[r] = mx;
            l_s[r] = l_s[r] * corr + sum;
            corr_s[r] = corr;
        }
        __syncthreads();

#pragma unroll
        for (int i = 0; i < 4; i++) {
            float cr = corr_s[ty + 16 * i];
#pragma unroll
            for (int j = 0; j < 8; j++) acc[i][j] *= cr;
        }

#pragma unroll 4
        for (int c = 0; c < 64; c++) {
            float4 v0 = *(float4*)&Vs[c * AD + tx * 8];
            float4 v1 = *(float4*)&Vs[c * AD + tx * 8 + 4];
#pragma unroll
            for (int i = 0; i < 4; i++) {
                float p = Ss[(ty + 16 * i) * SD + c];
                acc[i][0] = fmaf(p, v0.x, acc[i][0]);
                acc[i][1] = fmaf(p, v0.y, acc[i][1]);
                acc[i][2] = fmaf(p, v0.z, acc[i][2]);
                acc[i][3] = fmaf(p, v0.w, acc[i][3]);
                acc[i][4] = fmaf(p, v1.x, acc[i][4]);
                acc[i][5] = fmaf(p, v1.y, acc[i][5]);
                acc[i][6] = fmaf(p, v1.z, acc[i][6]);
                acc[i][7] = fmaf(p, v1.w, acc[i][7]);
            }
        }
        __syncthreads();
    }

#pragma unroll
    for (int i = 0; i < 4; i++) {
        int r = ty + 16 * i;
        float inv = 1.0f / l_s[r];
        float* cp = ctx + (qt * 64 + r) * DM + h * DH + tx * 8;
        *(float4*)cp       = make_float4(acc[i][0] * inv, acc[i][1] * inv,
                                         acc[i][2] * inv, acc[i][3] * inv);
        *(float4*)(cp + 4) = make_float4(acc[i][4] * inv, acc[i][5] * inv,
                                         acc[i][6] * inv, acc[i][7] * inv);
    }
}

// ---------------- launch ------------------------------------------------------
extern "C" void kernel_launch(void* const* d_in, const int* in_sizes, int n_in,
                              void* d_out, int out_size) {
    const float* resid = (const float*)d_in[0];
    const float* Wq    = (const float*)d_in[1];
    const float* Wk    = (const float*)d_in[2];
    const float* Wv    = (const float*)d_in[3];
    const float* Wo    = (const float*)d_in[4];
    float* out = (float*)d_out;

    float *gQ, *gK, *gV, *gC;
    cudaGetSymbolAddress((void**)&gQ, g_Q);
    cudaGetSymbolAddress((void**)&gK, g_K);
    cudaGetSymbolAddress((void**)&gV, g_V);
    cudaGetSymbolAddress((void**)&gC, g_ctx);
    __nv_bfloat16 *rhi, *rlo, *chi, *clo;
    __nv_bfloat16 *wqh, *wql, *wkh, *wkl, *wvh, *wvl, *woh, *wol;
    cudaGetSymbolAddress((void**)&rhi, g_r_hi);
    cudaGetSymbolAddress((void**)&rlo, g_r_lo);
    cudaGetSymbolAddress((void**)&chi, g_c_hi);
    cudaGetSymbolAddress((void**)&clo, g_c_lo);
    cudaGetSymbolAddress((void**)&wqh, g_Wq_hi);
    cudaGetSymbolAddress((void**)&wql, g_Wq_lo);
    cudaGetSymbolAddress((void**)&wkh, g_Wk_hi);
    cudaGetSymbolAddress((void**)&wkl, g_Wk_lo);
    cudaGetSymbolAddress((void**)&wvh, g_Wv_hi);
    cudaGetSymbolAddress((void**)&wvl, g_Wv_lo);
    cudaGetSymbolAddress((void**)&woh, g_Wo_hi);
    cudaGetSymbolAddress((void**)&wol, g_Wo_lo);

    cudaFuncSetAttribute(flash_kernel,
                         cudaFuncAttributeMaxDynamicSharedMemorySize, FLASH_SMEM);
    cudaFuncSetAttribute(gemm_mma_kernel,
                         cudaFuncAttributeMaxDynamicSharedMemorySize, GEMM_SMEM);

    init_freq_kernel<<<1, 64>>>();

    // prep: splits + weight transposes
    int nr = T_SEQ * DM;
    split_kernel<<<(nr + 255) / 256, 256>>>(resid, rhi, rlo, nr);
    dim3 tb(32, 8);
    transpose_split_kernel<<<dim3(DM / 32, DM / 32), tb>>>(Wq, wqh, wql, DM, DM);
    transpose_split_kernel<<<dim3(DKV / 32, DM / 32), tb>>>(Wk, wkh, wkl, DM, DKV);
    transpose_split_kernel<<<dim3(DKV / 32, DM / 32), tb>>>(Wv, wvh, wvl, DM, DKV);
    transpose_split_kernel<<<dim3(DM / 32, DM / 32), tb>>>(Wo, woh, wol, DM, DM);

    // projections on tensor cores (mma.sync)
    gemm_mma_kernel<<<dim3(DM / 128, T_SEQ / 128), 256, GEMM_SMEM>>>(
        rhi, rlo, wqh, wql, gQ, T_SEQ, DM, DM);
    gemm_mma_kernel<<<dim3(DKV / 128, T_SEQ / 128), 256, GEMM_SMEM>>>(
        rhi, rlo, wkh, wkl, gK, T_SEQ, DKV, DM);
    gemm_mma_kernel<<<dim3(DKV / 128, T_SEQ / 128), 256, GEMM_SMEM>>>(
        rhi, rlo, wvh, wvl, gV, T_SEQ, DKV, DM);

    int totQ = T_SEQ * NH * 64;
    rope_kernel<<<(totQ + 255) / 256, 256>>>(gQ, NH, totQ);
    int totK = T_SEQ * NKV * 64;
    rope_kernel<<<(totK + 255) / 256, 256>>>(gK, NKV, totK);

    flash_kernel<<<dim3(T_SEQ / 64, NH), 256, FLASH_SMEM>>>(gQ, gK, gV, gC);

    split_kernel<<<(nr + 255) / 256, 256>>>(gC, chi, clo, nr);
    gemm_mma_kernel<<<dim3(DM / 128, T_SEQ / 128), 256, GEMM_SMEM>>>(
        chi, clo, woh, wol, out, T_SEQ, DM, DM);
}